// round 1
// baseline (speedup 1.0000x reference)
#include <cuda_runtime.h>
#include <cuda_bf16.h>

#define NN 100000
#define EE 1600000
#define GG 256
#define HH 64
#define BN_EPS 1e-5f

// ---------------- scratch (device globals; no allocation) ----------------
__device__ int   g_deg[NN];
__device__ float g_dinv[NN];
__device__ float g_hs[NN * HH];    // (x @ W) * dinv[n]
__device__ float g_agg[NN * HH];   // edge-aggregated sums
__device__ float g_x[NN * HH];     // layer activations
__device__ float g_gsum[GG * HH];
__device__ int   g_gmax[GG * HH];  // float bits; values >= 0 so int max works
__device__ float g_gcnt[GG];

// ---------------- zeroing ----------------
__global__ void k_zero_misc() {
    int i = blockIdx.x * blockDim.x + threadIdx.x;
    if (i < NN) g_deg[i] = 0;
    if (i < GG * HH) { g_gsum[i] = 0.f; g_gmax[i] = 0; }
    if (i < GG) g_gcnt[i] = 0.f;
}

__global__ void k_zero_agg() {
    int i = blockIdx.x * blockDim.x + threadIdx.x;  // over NN*HH/4
    if (i < NN * HH / 4) ((float4*)g_agg)[i] = make_float4(0.f, 0.f, 0.f, 0.f);
}

// ---------------- degree / dinv ----------------
__global__ void k_deg(const int* __restrict__ ei) {
    int e = blockIdx.x * blockDim.x + threadIdx.x;
    if (e < EE) atomicAdd(&g_deg[ei[EE + e]], 1);
}

__global__ void k_dinv() {
    int n = blockIdx.x * blockDim.x + threadIdx.x;
    if (n < NN) g_dinv[n] = rsqrtf((float)g_deg[n] + 1.0f);
}

// ---------------- layer 0 GEMM: hs = (x[N,3] @ W0[3,64]) * dinv ----------------
__global__ void k_mm0(const float* __restrict__ x, const float* __restrict__ W0) {
    __shared__ float sW[3][64];
    int t = threadIdx.x;                 // 256 threads = 4 nodes x 64 dims
    if (t < 192) sW[t / 64][t % 64] = W0[t];
    int nl = t >> 6, j = t & 63;
    int n = blockIdx.x * 4 + nl;
    __syncthreads();
    if (n < NN) {
        float x0 = x[n * 3 + 0], x1 = x[n * 3 + 1], x2 = x[n * 3 + 2];
        float acc = x0 * sW[0][j] + x1 * sW[1][j] + x2 * sW[2][j];
        g_hs[n * 64 + j] = acc * g_dinv[n];
    }
}

// ---------------- layers 1,2 GEMM: hs = (g_x[N,64] @ W[64,64]) * dinv ----------------
__global__ void k_mm(const float* __restrict__ W) {
    __shared__ float sW[64][65];
    __shared__ float sx[4][64];
    int t = threadIdx.x;                 // 256 threads = 4 nodes x 64 dims
    for (int i = t; i < 4096; i += 256) sW[i >> 6][i & 63] = W[i];
    int nl = t >> 6, j = t & 63;
    int n = blockIdx.x * 4 + nl;
    sx[nl][j] = (n < NN) ? g_x[n * 64 + j] : 0.f;
    __syncthreads();
    if (n < NN) {
        float acc = 0.f;
#pragma unroll
        for (int k = 0; k < 64; k++) acc += sx[nl][k] * sW[k][j];
        g_hs[n * 64 + j] = acc * g_dinv[n];
    }
}

// ---------------- edge scatter: agg[dst] += hs[src] (vectorized RED) ----------------
__global__ void k_edge(const int* __restrict__ ei) {
    int gt = blockIdx.x * blockDim.x + threadIdx.x;   // EE*16 threads
    if (gt >= EE * 16) return;
    int e = gt >> 4, q = gt & 15;
    int s = ei[e];
    int d = ei[EE + e];
    float4 v = ((const float4*)g_hs)[s * 16 + q];
    float* ap = g_agg + d * 64 + q * 4;
    asm volatile("red.global.add.v4.f32 [%0], {%1, %2, %3, %4};"
                 :: "l"(ap), "f"(v.x), "f"(v.y), "f"(v.z), "f"(v.w) : "memory");
}

// ---------------- finalize: self-loop + bias + BN + ReLU -> g_x ----------------
__global__ void k_finalize(const float* __restrict__ b, const float* __restrict__ gm,
                           const float* __restrict__ be, const float* __restrict__ rm,
                           const float* __restrict__ rv) {
    int i = blockIdx.x * blockDim.x + threadIdx.x;    // NN*HH
    if (i >= NN * HH) return;
    int n = i >> 6, j = i & 63;
    float v = (g_agg[i] + g_hs[i]) * g_dinv[n] + b[j];
    v = (v - rm[j]) * rsqrtf(rv[j] + BN_EPS) * gm[j] + be[j];
    g_x[i] = fmaxf(v, 0.f);
}

// ---------------- pooling: sorted batch_idx -> run-length smem-free reduction ----------------
#define POOL_NB 128
__global__ void k_pool(const int* __restrict__ bidx) {
    int j = threadIdx.x;                // 64 threads = dims
    int n0 = blockIdx.x * POOL_NB;
    if (n0 >= NN) return;
    int cur = bidx[n0];
    float s = 0.f, mx = 0.f, c = 0.f;
    for (int i = 0; i < POOL_NB; i++) {
        int n = n0 + i;
        if (n >= NN) break;
        int gidx = bidx[n];
        if (gidx != cur) {
            atomicAdd(&g_gsum[cur * 64 + j], s);
            atomicMax(&g_gmax[cur * 64 + j], __float_as_int(mx));
            if (j == 0) atomicAdd(&g_gcnt[cur], c);
            cur = gidx; s = 0.f; mx = 0.f; c = 0.f;
        }
        float v = g_x[n * 64 + j];
        s += v;
        mx = fmaxf(mx, v);
        c += 1.f;
    }
    atomicAdd(&g_gsum[cur * 64 + j], s);
    atomicMax(&g_gmax[cur * 64 + j], __float_as_int(mx));
    if (j == 0) atomicAdd(&g_gcnt[cur], c);
}

// ---------------- MLP head: one block per graph ----------------
__global__ void k_mlp(const float* __restrict__ mW1, const float* __restrict__ mb1,
                      const float* __restrict__ mW2, const float* __restrict__ mb2,
                      const float* __restrict__ mW3, const float* __restrict__ mb3,
                      float* __restrict__ out) {
    __shared__ float xg[128];
    __shared__ float h1[32];
    __shared__ float h2[16];
    int g = blockIdx.x;
    int t = threadIdx.x;                // 32 threads
    float cnt = fmaxf(g_gcnt[g], 1.f);
    // build pooled features
    for (int j = t; j < 64; j += 32) {
        xg[j]      = g_gsum[g * 64 + j] / cnt;
        xg[64 + j] = __int_as_float(g_gmax[g * 64 + j]);
    }
    __syncthreads();
    // layer 1: 128 -> 32
    {
        float acc = mb1[t];
        for (int k = 0; k < 128; k++) acc += xg[k] * mW1[k * 32 + t];
        h1[t] = fmaxf(acc, 0.f);
    }
    __syncthreads();
    // layer 2: 32 -> 16
    if (t < 16) {
        float acc = mb2[t];
        for (int k = 0; k < 32; k++) acc += h1[k] * mW2[k * 16 + t];
        h2[t] = fmaxf(acc, 0.f);
    }
    __syncthreads();
    // layer 3: 16 -> 1
    if (t == 0) {
        float acc = mb3[0];
        for (int k = 0; k < 16; k++) acc += h2[k] * mW3[k];
        out[g] = acc;
    }
}

extern "C" void kernel_launch(void* const* d_in, const int* in_sizes, int n_in,
                              void* d_out, int out_size) {
    const float* x    = (const float*)d_in[0];
    const int*   ei   = (const int*)  d_in[1];
    const int*   bidx = (const int*)  d_in[2];
    const float* W[3]  = {(const float*)d_in[3],  (const float*)d_in[9],  (const float*)d_in[15]};
    const float* b[3]  = {(const float*)d_in[4],  (const float*)d_in[10], (const float*)d_in[16]};
    const float* gm[3] = {(const float*)d_in[5],  (const float*)d_in[11], (const float*)d_in[17]};
    const float* be[3] = {(const float*)d_in[6],  (const float*)d_in[12], (const float*)d_in[18]};
    const float* rm[3] = {(const float*)d_in[7],  (const float*)d_in[13], (const float*)d_in[19]};
    const float* rv[3] = {(const float*)d_in[8],  (const float*)d_in[14], (const float*)d_in[20]};
    const float* mW1 = (const float*)d_in[21];
    const float* mb1 = (const float*)d_in[22];
    const float* mW2 = (const float*)d_in[23];
    const float* mb2 = (const float*)d_in[24];
    const float* mW3 = (const float*)d_in[25];
    const float* mb3 = (const float*)d_in[26];
    float* out = (float*)d_out;

    const int T = 256;
    int zmBlocks   = (NN + T - 1) / T;               // covers NN > GG*HH
    int degBlocks  = (EE + T - 1) / T;
    int nBlocks    = (NN + T - 1) / T;
    int mmBlocks   = (NN + 3) / 4;
    int aggBlocks  = (NN * HH / 4 + T - 1) / T;
    int edgeBlocks = (EE * 16 + T - 1) / T;          // 100000 blocks
    int finBlocks  = (NN * HH + T - 1) / T;
    int poolBlocks = (NN + POOL_NB - 1) / POOL_NB;

    k_zero_misc<<<zmBlocks, T>>>();
    k_deg<<<degBlocks, T>>>(ei);
    k_dinv<<<nBlocks, T>>>();

    for (int l = 0; l < 3; l++) {
        if (l == 0) k_mm0<<<mmBlocks, T>>>(x, W[0]);
        else        k_mm<<<mmBlocks, T>>>(W[l]);
        k_zero_agg<<<aggBlocks, T>>>();
        k_edge<<<edgeBlocks, T>>>(ei);
        k_finalize<<<finBlocks, T>>>(b[l], gm[l], be[l], rm[l], rv[l]);
    }

    k_pool<<<poolBlocks, 64>>>(bidx);
    k_mlp<<<GG, 32>>>(mW1, mb1, mW2, mb2, mW3, mb3, out);
}

// round 2
// speedup vs baseline: 1.4799x; 1.4799x over previous
#include <cuda_runtime.h>
#include <cuda_bf16.h>

#define NN 100000
#define EE 1600000
#define GG 256
#define HH 64
#define BN_EPS 1e-5f
#define SCAN_BS 512
#define SCAN_NB ((NN + SCAN_BS - 1) / SCAN_BS)   // 196

// ---------------- scratch (device globals; no allocation) ----------------
__device__ int   g_deg[NN];
__device__ float g_dinv[NN];
__device__ float g_hs[NN * HH];      // (x @ W) * dinv[n]
__device__ float g_x[NN * HH];       // layer activations
__device__ int   g_rowptr[NN + 1];   // CSR by dst
__device__ int   g_cursor[NN];
__device__ int   g_csrsrc[EE];
__device__ int   g_ptmp[NN];         // inclusive scan within block
__device__ int   g_bsum[SCAN_NB];    // per-block sums
__device__ int   g_boff[SCAN_NB];    // exclusive block offsets
__device__ float g_gsum[GG * HH];
__device__ int   g_gmax[GG * HH];
__device__ float g_gcnt[GG];

// ---------------- zeroing ----------------
__global__ void k_zero_misc() {
    int i = blockIdx.x * blockDim.x + threadIdx.x;
    if (i < NN) g_deg[i] = 0;
    if (i < GG * HH) { g_gsum[i] = 0.f; g_gmax[i] = 0; }
    if (i < GG) g_gcnt[i] = 0.f;
}

// ---------------- degree histogram (by dst) ----------------
__global__ void k_deg(const int* __restrict__ ei) {
    int e = blockIdx.x * blockDim.x + threadIdx.x;
    if (e < EE) atomicAdd(&g_deg[ei[EE + e]], 1);
}

__global__ void k_dinv() {
    int n = blockIdx.x * blockDim.x + threadIdx.x;
    if (n < NN) g_dinv[n] = rsqrtf((float)g_deg[n] + 1.0f);
}

// ---------------- prefix scan (3 kernels) ----------------
__global__ void k_scan1() {
    __shared__ int s[SCAN_BS];
    int i = blockIdx.x * SCAN_BS + threadIdx.x;
    int v = (i < NN) ? g_deg[i] : 0;
    s[threadIdx.x] = v;
    __syncthreads();
    for (int off = 1; off < SCAN_BS; off <<= 1) {
        int t = s[threadIdx.x];
        if (threadIdx.x >= off) t += s[threadIdx.x - off];
        __syncthreads();
        s[threadIdx.x] = t;
        __syncthreads();
    }
    if (i < NN) g_ptmp[i] = s[threadIdx.x];
    if (threadIdx.x == SCAN_BS - 1) g_bsum[blockIdx.x] = s[threadIdx.x];
}

__global__ void k_scan2() {       // single block of 256 threads, SCAN_NB=196 <= 256
    __shared__ int s[256];
    int t = threadIdx.x;
    s[t] = (t < SCAN_NB) ? g_bsum[t] : 0;
    __syncthreads();
    for (int off = 1; off < 256; off <<= 1) {
        int v = s[t];
        if (t >= off) v += s[t - off];
        __syncthreads();
        s[t] = v;
        __syncthreads();
    }
    if (t < SCAN_NB) g_boff[t] = s[t] - g_bsum[t];   // exclusive
}

__global__ void k_scan3() {
    int i = blockIdx.x * SCAN_BS + threadIdx.x;
    if (i < NN) {
        int excl = g_ptmp[i] + g_boff[blockIdx.x] - g_deg[i];
        g_rowptr[i] = excl;
        g_cursor[i] = excl;
    }
    if (i == 0) g_rowptr[NN] = EE;
}

// ---------------- CSR fill: csrsrc grouped by dst ----------------
__global__ void k_csr(const int* __restrict__ ei) {
    int e = blockIdx.x * blockDim.x + threadIdx.x;
    if (e < EE) {
        int s = ei[e];
        int d = ei[EE + e];
        int p = atomicAdd(&g_cursor[d], 1);
        g_csrsrc[p] = s;
    }
}

// ---------------- layer 0 GEMM: hs = (x[N,3] @ W0[3,64]) * dinv ----------------
__global__ void k_mm0(const float* __restrict__ x, const float* __restrict__ W0) {
    __shared__ float sW[3][64];
    int t = threadIdx.x;                 // 256 threads = 4 nodes x 64 dims
    if (t < 192) sW[t / 64][t % 64] = W0[t];
    int nl = t >> 6, j = t & 63;
    int n = blockIdx.x * 4 + nl;
    __syncthreads();
    if (n < NN) {
        float x0 = x[n * 3 + 0], x1 = x[n * 3 + 1], x2 = x[n * 3 + 2];
        float acc = x0 * sW[0][j] + x1 * sW[1][j] + x2 * sW[2][j];
        g_hs[n * 64 + j] = acc * g_dinv[n];
    }
}

// ---------------- layers 1,2 GEMM: hs = (g_x[N,64] @ W[64,64]) * dinv ----------------
__global__ void k_mm(const float* __restrict__ W) {
    __shared__ float sW[64][65];
    __shared__ float sx[4][64];
    int t = threadIdx.x;                 // 256 threads = 4 nodes x 64 dims
    for (int i = t; i < 4096; i += 256) sW[i >> 6][i & 63] = W[i];
    int nl = t >> 6, j = t & 63;
    int n = blockIdx.x * 4 + nl;
    sx[nl][j] = (n < NN) ? g_x[n * 64 + j] : 0.f;
    __syncthreads();
    if (n < NN) {
        float acc = 0.f;
#pragma unroll
        for (int k = 0; k < 64; k++) acc += sx[nl][k] * sW[k][j];
        g_hs[n * 64 + j] = acc * g_dinv[n];
    }
}

// ---------------- gather + finalize: pull-mode aggregation, no atomics ----------------
// 16 threads per node (each owns a float4 of the 64-dim row); 256 threads = 16 nodes/block.
__global__ void __launch_bounds__(256) k_gather(
        const float* __restrict__ b, const float* __restrict__ gm,
        const float* __restrict__ be, const float* __restrict__ rm,
        const float* __restrict__ rv) {
    int t = threadIdx.x;
    int q = t & 15;
    int node = blockIdx.x * 16 + (t >> 4);
    if (node >= NN) return;

    int j = q * 4;
    // BN affine folded: out = relu(acc*dinv*sc + sh)
    float4 sc, sh;
    sc.x = gm[j + 0] * rsqrtf(rv[j + 0] + BN_EPS);
    sc.y = gm[j + 1] * rsqrtf(rv[j + 1] + BN_EPS);
    sc.z = gm[j + 2] * rsqrtf(rv[j + 2] + BN_EPS);
    sc.w = gm[j + 3] * rsqrtf(rv[j + 3] + BN_EPS);
    sh.x = (b[j + 0] - rm[j + 0]) * sc.x + be[j + 0];
    sh.y = (b[j + 1] - rm[j + 1]) * sc.y + be[j + 1];
    sh.z = (b[j + 2] - rm[j + 2]) * sc.z + be[j + 2];
    sh.w = (b[j + 3] - rm[j + 3]) * sc.w + be[j + 3];

    const float4* hs4 = (const float4*)g_hs;
    float4 acc = hs4[node * 16 + q];     // self-loop term (hs = h*dinv)

    int beg = g_rowptr[node], end = g_rowptr[node + 1];
    int k = beg;
    int s = (k < end) ? g_csrsrc[k] : 0;
    while (k < end) {
        int s2 = (k + 1 < end) ? g_csrsrc[k + 1] : 0;
        float4 v = hs4[s * 16 + q];
        acc.x += v.x; acc.y += v.y; acc.z += v.z; acc.w += v.w;
        s = s2;
        ++k;
    }

    float dv = g_dinv[node];
    float4 o;
    o.x = fmaxf(fmaf(acc.x * dv, sc.x, sh.x), 0.f);
    o.y = fmaxf(fmaf(acc.y * dv, sc.y, sh.y), 0.f);
    o.z = fmaxf(fmaf(acc.z * dv, sc.z, sh.z), 0.f);
    o.w = fmaxf(fmaf(acc.w * dv, sc.w, sh.w), 0.f);
    ((float4*)g_x)[node * 16 + q] = o;
}

// ---------------- pooling: sorted batch_idx -> run-length reduction ----------------
#define POOL_NB 128
__global__ void k_pool(const int* __restrict__ bidx) {
    int j = threadIdx.x;                // 64 threads = dims
    int n0 = blockIdx.x * POOL_NB;
    if (n0 >= NN) return;
    int cur = bidx[n0];
    float s = 0.f, mx = 0.f, c = 0.f;
    for (int i = 0; i < POOL_NB; i++) {
        int n = n0 + i;
        if (n >= NN) break;
        int gidx = bidx[n];
        if (gidx != cur) {
            atomicAdd(&g_gsum[cur * 64 + j], s);
            atomicMax(&g_gmax[cur * 64 + j], __float_as_int(mx));
            if (j == 0) atomicAdd(&g_gcnt[cur], c);
            cur = gidx; s = 0.f; mx = 0.f; c = 0.f;
        }
        float v = g_x[n * 64 + j];
        s += v;
        mx = fmaxf(mx, v);
        c += 1.f;
    }
    atomicAdd(&g_gsum[cur * 64 + j], s);
    atomicMax(&g_gmax[cur * 64 + j], __float_as_int(mx));
    if (j == 0) atomicAdd(&g_gcnt[cur], c);
}

// ---------------- MLP head: one block per graph ----------------
__global__ void k_mlp(const float* __restrict__ mW1, const float* __restrict__ mb1,
                      const float* __restrict__ mW2, const float* __restrict__ mb2,
                      const float* __restrict__ mW3, const float* __restrict__ mb3,
                      float* __restrict__ out) {
    __shared__ float xg[128];
    __shared__ float h1[32];
    __shared__ float h2[16];
    int g = blockIdx.x;
    int t = threadIdx.x;                // 32 threads
    float cnt = fmaxf(g_gcnt[g], 1.f);
    for (int j = t; j < 64; j += 32) {
        xg[j]      = g_gsum[g * 64 + j] / cnt;
        xg[64 + j] = __int_as_float(g_gmax[g * 64 + j]);
    }
    __syncthreads();
    {
        float acc = mb1[t];
        for (int k = 0; k < 128; k++) acc += xg[k] * mW1[k * 32 + t];
        h1[t] = fmaxf(acc, 0.f);
    }
    __syncthreads();
    if (t < 16) {
        float acc = mb2[t];
        for (int k = 0; k < 32; k++) acc += h1[k] * mW2[k * 16 + t];
        h2[t] = fmaxf(acc, 0.f);
    }
    __syncthreads();
    if (t == 0) {
        float acc = mb3[0];
        for (int k = 0; k < 16; k++) acc += h2[k] * mW3[k];
        out[g] = acc;
    }
}

extern "C" void kernel_launch(void* const* d_in, const int* in_sizes, int n_in,
                              void* d_out, int out_size) {
    const float* x    = (const float*)d_in[0];
    const int*   ei   = (const int*)  d_in[1];
    const int*   bidx = (const int*)  d_in[2];
    const float* W[3]  = {(const float*)d_in[3],  (const float*)d_in[9],  (const float*)d_in[15]};
    const float* b[3]  = {(const float*)d_in[4],  (const float*)d_in[10], (const float*)d_in[16]};
    const float* gm[3] = {(const float*)d_in[5],  (const float*)d_in[11], (const float*)d_in[17]};
    const float* be[3] = {(const float*)d_in[6],  (const float*)d_in[12], (const float*)d_in[18]};
    const float* rm[3] = {(const float*)d_in[7],  (const float*)d_in[13], (const float*)d_in[19]};
    const float* rv[3] = {(const float*)d_in[8],  (const float*)d_in[14], (const float*)d_in[20]};
    const float* mW1 = (const float*)d_in[21];
    const float* mb1 = (const float*)d_in[22];
    const float* mW2 = (const float*)d_in[23];
    const float* mb2 = (const float*)d_in[24];
    const float* mW3 = (const float*)d_in[25];
    const float* mb3 = (const float*)d_in[26];
    float* out = (float*)d_out;

    const int T = 256;
    int zmBlocks   = (NN + T - 1) / T;
    int degBlocks  = (EE + T - 1) / T;
    int nBlocks    = (NN + T - 1) / T;
    int mmBlocks   = (NN + 3) / 4;
    int gatBlocks  = (NN + 15) / 16;
    int poolBlocks = (NN + POOL_NB - 1) / POOL_NB;

    k_zero_misc<<<zmBlocks, T>>>();
    k_deg<<<degBlocks, T>>>(ei);
    k_dinv<<<nBlocks, T>>>();
    k_scan1<<<SCAN_NB, SCAN_BS>>>();
    k_scan2<<<1, 256>>>();
    k_scan3<<<SCAN_NB, SCAN_BS>>>();
    k_csr<<<degBlocks, T>>>(ei);

    for (int l = 0; l < 3; l++) {
        if (l == 0) k_mm0<<<mmBlocks, T>>>(x, W[0]);
        else        k_mm<<<mmBlocks, T>>>(W[l]);
        k_gather<<<gatBlocks, T>>>(b[l], gm[l], be[l], rm[l], rv[l]);
    }

    k_pool<<<poolBlocks, 64>>>(bidx);
    k_mlp<<<GG, 32>>>(mW1, mb1, mW2, mb2, mW3, mb3, out);
}

// round 3
// speedup vs baseline: 2.0005x; 1.3518x over previous
#include <cuda_runtime.h>
#include <cuda_bf16.h>

#define NN 100000
#define EE 1600000
#define GG 256
#define HH 64
#define BN_EPS 1e-5f
#define SCAN_BS 512
#define SCAN_NB ((NN + SCAN_BS - 1) / SCAN_BS)   // 196

// ---------------- scratch (device globals; no allocation) ----------------
__device__ int   g_deg[NN];
__device__ float g_dinv[NN];
__device__ float g_hs[NN * HH];      // (x @ W) * dinv[n]
__device__ float g_x[NN * HH];       // layer activations
__device__ int   g_rowptr[NN + 1];   // CSR by dst
__device__ int   g_cursor[NN];
__device__ int   g_csrsrc[EE];
__device__ int   g_ptmp[NN];
__device__ int   g_bsum[SCAN_NB];
__device__ int   g_boff[SCAN_NB];
__device__ float g_gsum[GG * HH];
__device__ int   g_gmax[GG * HH];
__device__ float g_gcnt[GG];

// ---------------- zeroing ----------------
__global__ void k_zero_misc() {
    int i = blockIdx.x * blockDim.x + threadIdx.x;
    if (i < NN) g_deg[i] = 0;
    if (i < GG * HH) { g_gsum[i] = 0.f; g_gmax[i] = 0; }
    if (i < GG) g_gcnt[i] = 0.f;
}

// ---------------- degree histogram (by dst) ----------------
__global__ void k_deg(const int* __restrict__ ei) {
    int e = blockIdx.x * blockDim.x + threadIdx.x;
    if (e < EE) atomicAdd(&g_deg[ei[EE + e]], 1);
}

// ---------------- prefix scan (3 kernels); dinv fused into scan3 ----------------
__global__ void k_scan1() {
    __shared__ int s[SCAN_BS];
    int i = blockIdx.x * SCAN_BS + threadIdx.x;
    int v = (i < NN) ? g_deg[i] : 0;
    s[threadIdx.x] = v;
    __syncthreads();
    for (int off = 1; off < SCAN_BS; off <<= 1) {
        int t = s[threadIdx.x];
        if (threadIdx.x >= off) t += s[threadIdx.x - off];
        __syncthreads();
        s[threadIdx.x] = t;
        __syncthreads();
    }
    if (i < NN) g_ptmp[i] = s[threadIdx.x];
    if (threadIdx.x == SCAN_BS - 1) g_bsum[blockIdx.x] = s[threadIdx.x];
}

__global__ void k_scan2() {       // single block, SCAN_NB=196 <= 256
    __shared__ int s[256];
    int t = threadIdx.x;
    s[t] = (t < SCAN_NB) ? g_bsum[t] : 0;
    __syncthreads();
    for (int off = 1; off < 256; off <<= 1) {
        int v = s[t];
        if (t >= off) v += s[t - off];
        __syncthreads();
        s[t] = v;
        __syncthreads();
    }
    if (t < SCAN_NB) g_boff[t] = s[t] - g_bsum[t];   // exclusive
}

__global__ void k_scan3() {
    int i = blockIdx.x * SCAN_BS + threadIdx.x;
    if (i < NN) {
        int d = g_deg[i];
        int excl = g_ptmp[i] + g_boff[blockIdx.x] - d;
        g_rowptr[i] = excl;
        g_cursor[i] = excl;
        g_dinv[i] = rsqrtf((float)d + 1.0f);
    }
    if (i == 0) g_rowptr[NN] = EE;
}

// ---------------- CSR fill ----------------
__global__ void k_csr(const int* __restrict__ ei) {
    int e = blockIdx.x * blockDim.x + threadIdx.x;
    if (e < EE) {
        int s = ei[e];
        int d = ei[EE + e];
        int p = atomicAdd(&g_cursor[d], 1);
        g_csrsrc[p] = s;
    }
}

// ---------------- layer 0 GEMM: hs = (x[N,3] @ W0[3,64]) * dinv ----------------
// 256 threads = 16 nodes x 16 float4-cols.
__global__ void __launch_bounds__(256) k_mm0(const float* __restrict__ x,
                                             const float* __restrict__ W0) {
    __shared__ float4 sW4[3][16];
    __shared__ float  sxx[48];
    int t = threadIdx.x;
    if (t < 48) {
        sW4[t / 16][t % 16] = ((const float4*)W0)[t];
        int gi = blockIdx.x * 48 + t;
        sxx[t] = (gi < NN * 3) ? x[gi] : 0.f;
    }
    __syncthreads();
    int nl = t >> 4, q = t & 15;
    int n = blockIdx.x * 16 + nl;
    if (n >= NN) return;
    float x0 = sxx[nl * 3 + 0], x1 = sxx[nl * 3 + 1], x2 = sxx[nl * 3 + 2];
    float4 w0 = sW4[0][q], w1 = sW4[1][q], w2 = sW4[2][q];
    float dv = g_dinv[n];
    float4 o;
    o.x = (x0 * w0.x + x1 * w1.x + x2 * w2.x) * dv;
    o.y = (x0 * w0.y + x1 * w1.y + x2 * w2.y) * dv;
    o.z = (x0 * w0.z + x1 * w1.z + x2 * w2.z) * dv;
    o.w = (x0 * w0.w + x1 * w1.w + x2 * w2.w) * dv;
    ((float4*)g_hs)[n * 16 + q] = o;
}

// ---------------- layers 1,2 GEMM: hs = (g_x @ W) * dinv ----------------
// 256 threads = 16 nodes x 16 float4-cols; LDS.128 on W, broadcast LDS on x.
__global__ void __launch_bounds__(256) k_mm(const float* __restrict__ W) {
    __shared__ float4 sW4[64][16];
    __shared__ float4 sx4[16][17];   // pad row to 17 float4 (68 floats) -> no bank conflict
    int t = threadIdx.x;
    int nl = t >> 4, q = t & 15;
#pragma unroll
    for (int i = t; i < 1024; i += 256) sW4[i >> 4][i & 15] = ((const float4*)W)[i];
    int n = blockIdx.x * 16 + nl;
    sx4[nl][q] = (n < NN) ? ((const float4*)g_x)[n * 16 + q]
                          : make_float4(0.f, 0.f, 0.f, 0.f);
    __syncthreads();
    if (n >= NN) return;
    const float* xrow = (const float*)sx4[nl];
    float4 acc = make_float4(0.f, 0.f, 0.f, 0.f);
#pragma unroll
    for (int k = 0; k < 64; k++) {
        float xk = xrow[k];
        float4 w = sW4[k][q];
        acc.x = fmaf(xk, w.x, acc.x);
        acc.y = fmaf(xk, w.y, acc.y);
        acc.z = fmaf(xk, w.z, acc.z);
        acc.w = fmaf(xk, w.w, acc.w);
    }
    float dv = g_dinv[n];
    acc.x *= dv; acc.y *= dv; acc.z *= dv; acc.w *= dv;
    ((float4*)g_hs)[n * 16 + q] = acc;
}

// ---------------- gather + finalize: pull-mode, 32 lanes/node, float2 ----------------
__global__ void __launch_bounds__(256) k_gather(
        const float* __restrict__ b, const float* __restrict__ gm,
        const float* __restrict__ be, const float* __restrict__ rm,
        const float* __restrict__ rv) {
    int lane = threadIdx.x & 31;
    int node = blockIdx.x * 8 + (threadIdx.x >> 5);
    if (node >= NN) return;

    int j = lane * 2;
    float scx = gm[j] * rsqrtf(rv[j] + BN_EPS);
    float scy = gm[j + 1] * rsqrtf(rv[j + 1] + BN_EPS);
    float shx = (b[j] - rm[j]) * scx + be[j];
    float shy = (b[j + 1] - rm[j + 1]) * scy + be[j + 1];

    const float2* hs2 = (const float2*)g_hs;
    float2 acc = hs2[node * 32 + lane];      // self-loop term (hs = h*dinv)

    int beg = g_rowptr[node], end = g_rowptr[node + 1];
    const int* __restrict__ idx = g_csrsrc;
    int k = beg;
    for (; k + 4 <= end; k += 4) {
        int s0 = idx[k], s1 = idx[k + 1], s2 = idx[k + 2], s3 = idx[k + 3];
        float2 v0 = hs2[s0 * 32 + lane];
        float2 v1 = hs2[s1 * 32 + lane];
        float2 v2 = hs2[s2 * 32 + lane];
        float2 v3 = hs2[s3 * 32 + lane];
        acc.x += (v0.x + v1.x) + (v2.x + v3.x);
        acc.y += (v0.y + v1.y) + (v2.y + v3.y);
    }
    for (; k < end; k++) {
        float2 v = hs2[idx[k] * 32 + lane];
        acc.x += v.x; acc.y += v.y;
    }

    float dv = g_dinv[node];
    float2 o;
    o.x = fmaxf(fmaf(acc.x * dv, scx, shx), 0.f);
    o.y = fmaxf(fmaf(acc.y * dv, scy, shy), 0.f);
    ((float2*)g_x)[node * 32 + lane] = o;
}

// ---------------- pooling: sorted batch_idx -> run-length reduction ----------------
#define POOL_NB 128
__global__ void k_pool(const int* __restrict__ bidx) {
    int j = threadIdx.x;                // 64 threads = dims
    int n0 = blockIdx.x * POOL_NB;
    if (n0 >= NN) return;
    int cur = bidx[n0];
    float s = 0.f, mx = 0.f, c = 0.f;
    for (int i = 0; i < POOL_NB; i++) {
        int n = n0 + i;
        if (n >= NN) break;
        int gidx = bidx[n];
        if (gidx != cur) {
            atomicAdd(&g_gsum[cur * 64 + j], s);
            atomicMax(&g_gmax[cur * 64 + j], __float_as_int(mx));
            if (j == 0) atomicAdd(&g_gcnt[cur], c);
            cur = gidx; s = 0.f; mx = 0.f; c = 0.f;
        }
        float v = g_x[n * 64 + j];
        s += v;
        mx = fmaxf(mx, v);
        c += 1.f;
    }
    atomicAdd(&g_gsum[cur * 64 + j], s);
    atomicMax(&g_gmax[cur * 64 + j], __float_as_int(mx));
    if (j == 0) atomicAdd(&g_gcnt[cur], c);
}

// ---------------- MLP head ----------------
__global__ void k_mlp(const float* __restrict__ mW1, const float* __restrict__ mb1,
                      const float* __restrict__ mW2, const float* __restrict__ mb2,
                      const float* __restrict__ mW3, const float* __restrict__ mb3,
                      float* __restrict__ out) {
    __shared__ float xg[128];
    __shared__ float h1[32];
    __shared__ float h2[16];
    int g = blockIdx.x;
    int t = threadIdx.x;                // 32 threads
    float cnt = fmaxf(g_gcnt[g], 1.f);
    for (int j = t; j < 64; j += 32) {
        xg[j]      = g_gsum[g * 64 + j] / cnt;
        xg[64 + j] = __int_as_float(g_gmax[g * 64 + j]);
    }
    __syncthreads();
    {
        float acc = mb1[t];
        for (int k = 0; k < 128; k++) acc += xg[k] * mW1[k * 32 + t];
        h1[t] = fmaxf(acc, 0.f);
    }
    __syncthreads();
    if (t < 16) {
        float acc = mb2[t];
        for (int k = 0; k < 32; k++) acc += h1[k] * mW2[k * 16 + t];
        h2[t] = fmaxf(acc, 0.f);
    }
    __syncthreads();
    if (t == 0) {
        float acc = mb3[0];
        for (int k = 0; k < 16; k++) acc += h2[k] * mW3[k];
        out[g] = acc;
    }
}

extern "C" void kernel_launch(void* const* d_in, const int* in_sizes, int n_in,
                              void* d_out, int out_size) {
    const float* x    = (const float*)d_in[0];
    const int*   ei   = (const int*)  d_in[1];
    const int*   bidx = (const int*)  d_in[2];
    const float* W[3]  = {(const float*)d_in[3],  (const float*)d_in[9],  (const float*)d_in[15]};
    const float* b[3]  = {(const float*)d_in[4],  (const float*)d_in[10], (const float*)d_in[16]};
    const float* gm[3] = {(const float*)d_in[5],  (const float*)d_in[11], (const float*)d_in[17]};
    const float* be[3] = {(const float*)d_in[6],  (const float*)d_in[12], (const float*)d_in[18]};
    const float* rm[3] = {(const float*)d_in[7],  (const float*)d_in[13], (const float*)d_in[19]};
    const float* rv[3] = {(const float*)d_in[8],  (const float*)d_in[14], (const float*)d_in[20]};
    const float* mW1 = (const float*)d_in[21];
    const float* mb1 = (const float*)d_in[22];
    const float* mW2 = (const float*)d_in[23];
    const float* mb2 = (const float*)d_in[24];
    const float* mW3 = (const float*)d_in[25];
    const float* mb3 = (const float*)d_in[26];
    float* out = (float*)d_out;

    const int T = 256;
    int zmBlocks   = (NN + T - 1) / T;
    int degBlocks  = (EE + T - 1) / T;
    int mmBlocks   = (NN + 15) / 16;
    int gatBlocks  = (NN + 7) / 8;
    int poolBlocks = (NN + POOL_NB - 1) / POOL_NB;

    k_zero_misc<<<zmBlocks, T>>>();
    k_deg<<<degBlocks, T>>>(ei);
    k_scan1<<<SCAN_NB, SCAN_BS>>>();
    k_scan2<<<1, 256>>>();
    k_scan3<<<SCAN_NB, SCAN_BS>>>();
    k_csr<<<degBlocks, T>>>(ei);

    for (int l = 0; l < 3; l++) {
        if (l == 0) k_mm0<<<mmBlocks, T>>>(x, W[0]);
        else        k_mm<<<mmBlocks, T>>>(W[l]);
        k_gather<<<gatBlocks, T>>>(b[l], gm[l], be[l], rm[l], rv[l]);
    }

    k_pool<<<poolBlocks, 64>>>(bidx);
    k_mlp<<<GG, 32>>>(mW1, mb1, mW2, mb2, mW3, mb3, out);
}

// round 4
// speedup vs baseline: 2.3557x; 1.1775x over previous
#include <cuda_runtime.h>
#include <cuda_bf16.h>

#define NN 100000
#define EE 1600000
#define GG 256
#define HH 64
#define BN_EPS 1e-5f
#define SCAN_BS 512
#define SCAN_NB ((NN + SCAN_BS - 1) / SCAN_BS)   // 196

// ---------------- scratch (device globals; no allocation) ----------------
__device__ int    g_deg[NN];
__device__ float  g_dinv[NN];
__device__ float4 g_xs[NN];          // dinv * x (3-wide, w=0)
__device__ float4 g_aggx[NN];        // layer-0 aggregated input features
__device__ float  g_hs[NN * HH];     // (x @ W) * dinv
__device__ float  g_x[NN * HH];      // layer activations
__device__ int    g_rowptr[NN + 1];
__device__ int    g_cursor[NN];
__device__ int    g_csrsrc[EE];
__device__ int    g_ptmp[NN];
__device__ int    g_bsum[SCAN_NB];
__device__ float  g_gsum[GG * HH];
__device__ int    g_gmax[GG * HH];
__device__ float  g_gcnt[GG];

// ---------------- zeroing ----------------
__global__ void k_zero_misc() {
    int i = blockIdx.x * blockDim.x + threadIdx.x;
    if (i < NN) g_deg[i] = 0;
    if (i < GG * HH) { g_gsum[i] = 0.f; g_gmax[i] = 0; }
    if (i < GG) g_gcnt[i] = 0.f;
}

// ---------------- degree histogram (by dst) ----------------
__global__ void k_deg(const int* __restrict__ ei) {
    int e = blockIdx.x * blockDim.x + threadIdx.x;
    if (e < EE) atomicAdd(&g_deg[ei[EE + e]], 1);
}

// ---------------- scan part 1: per-block inclusive scan + block sums ----------------
__global__ void k_scan1() {
    __shared__ int s[SCAN_BS];
    int i = blockIdx.x * SCAN_BS + threadIdx.x;
    int v = (i < NN) ? g_deg[i] : 0;
    s[threadIdx.x] = v;
    __syncthreads();
    for (int off = 1; off < SCAN_BS; off <<= 1) {
        int t = s[threadIdx.x];
        if (threadIdx.x >= off) t += s[threadIdx.x - off];
        __syncthreads();
        s[threadIdx.x] = t;
        __syncthreads();
    }
    if (i < NN) g_ptmp[i] = s[threadIdx.x];
    if (threadIdx.x == SCAN_BS - 1) g_bsum[blockIdx.x] = s[threadIdx.x];
}

// ---------------- scan part 2 (fused): block offset + rowptr/cursor/dinv/xs ----------------
__global__ void k_scan23(const float* __restrict__ x) {
    __shared__ int r[SCAN_BS];
    int t = threadIdx.x;
    // exclusive offset for this block = sum of bsum[j], j < blockIdx.x
    r[t] = (t < SCAN_NB && t < blockIdx.x) ? g_bsum[t] : 0;
    __syncthreads();
    for (int off = SCAN_BS / 2; off > 0; off >>= 1) {
        if (t < off) r[t] += r[t + off];
        __syncthreads();
    }
    int boff = r[0];
    int i = blockIdx.x * SCAN_BS + t;
    if (i < NN) {
        int d = g_deg[i];
        int excl = g_ptmp[i] + boff - d;
        g_rowptr[i] = excl;
        g_cursor[i] = excl;
        float dv = rsqrtf((float)d + 1.0f);
        g_dinv[i] = dv;
        g_xs[i] = make_float4(x[i * 3] * dv, x[i * 3 + 1] * dv, x[i * 3 + 2] * dv, 0.f);
    }
    if (i == 0) g_rowptr[NN] = EE;
}

// ---------------- CSR fill ----------------
__global__ void k_csr(const int* __restrict__ ei) {
    int e = blockIdx.x * blockDim.x + threadIdx.x;
    if (e < EE) {
        int s = ei[e];
        int d = ei[EE + e];
        int p = atomicAdd(&g_cursor[d], 1);
        g_csrsrc[p] = s;
    }
}

// ---------------- layer-0 gather in INPUT space (3-wide): tiny traffic ----------------
__global__ void k_gather3() {
    int node = blockIdx.x * blockDim.x + threadIdx.x;
    if (node >= NN) return;
    float4 acc = g_xs[node];                 // self term xs_d
    int beg = g_rowptr[node], end = g_rowptr[node + 1];
    const int* __restrict__ idx = g_csrsrc;
    int k = beg;
    for (; k + 4 <= end; k += 4) {
        int s0 = idx[k], s1 = idx[k + 1], s2 = idx[k + 2], s3 = idx[k + 3];
        float4 a = g_xs[s0], b = g_xs[s1], c = g_xs[s2], d = g_xs[s3];
        acc.x += (a.x + b.x) + (c.x + d.x);
        acc.y += (a.y + b.y) + (c.y + d.y);
        acc.z += (a.z + b.z) + (c.z + d.z);
    }
    for (; k < end; k++) {
        float4 a = g_xs[idx[k]];
        acc.x += a.x; acc.y += a.y; acc.z += a.z;
    }
    float dv = g_dinv[node];
    g_aggx[node] = make_float4(acc.x * dv, acc.y * dv, acc.z * dv, 0.f);
}

// ---------------- layer-0 GEMM + bias + BN + ReLU -> g_x ----------------
// 256 threads = 16 nodes x 16 float4-cols
__global__ void __launch_bounds__(256) k_mm0f(const float* __restrict__ W0,
        const float* __restrict__ b, const float* __restrict__ gm,
        const float* __restrict__ be, const float* __restrict__ rm,
        const float* __restrict__ rv) {
    __shared__ float4 sW4[3][16];
    __shared__ float4 sxa[16];
    int t = threadIdx.x;
    if (t < 48) sW4[t / 16][t % 16] = ((const float4*)W0)[t];
    if (t < 16) {
        int gn = blockIdx.x * 16 + t;
        sxa[t] = (gn < NN) ? g_aggx[gn] : make_float4(0.f, 0.f, 0.f, 0.f);
    }
    __syncthreads();
    int nl = t >> 4, q = t & 15;
    int n = blockIdx.x * 16 + nl;
    if (n >= NN) return;
    int j = q * 4;
    float4 sc, sh;
    sc.x = gm[j] * rsqrtf(rv[j] + BN_EPS);
    sc.y = gm[j + 1] * rsqrtf(rv[j + 1] + BN_EPS);
    sc.z = gm[j + 2] * rsqrtf(rv[j + 2] + BN_EPS);
    sc.w = gm[j + 3] * rsqrtf(rv[j + 3] + BN_EPS);
    sh.x = (b[j] - rm[j]) * sc.x + be[j];
    sh.y = (b[j + 1] - rm[j + 1]) * sc.y + be[j + 1];
    sh.z = (b[j + 2] - rm[j + 2]) * sc.z + be[j + 2];
    sh.w = (b[j + 3] - rm[j + 3]) * sc.w + be[j + 3];
    float4 a = sxa[nl];
    float4 w0 = sW4[0][q], w1 = sW4[1][q], w2 = sW4[2][q];
    float4 o;
    o.x = fmaxf(fmaf(a.x * w0.x + a.y * w1.x + a.z * w2.x, sc.x, sh.x), 0.f);
    o.y = fmaxf(fmaf(a.x * w0.y + a.y * w1.y + a.z * w2.y, sc.y, sh.y), 0.f);
    o.z = fmaxf(fmaf(a.x * w0.z + a.y * w1.z + a.z * w2.z, sc.z, sh.z), 0.f);
    o.w = fmaxf(fmaf(a.x * w0.w + a.y * w1.w + a.z * w2.w, sc.w, sh.w), 0.f);
    ((float4*)g_x)[n * 16 + q] = o;
}

// ---------------- layers 1,2 GEMM: hs = (g_x @ W) * dinv ; packed f32x2 ----------------
// 256 threads = 64 nodes/block; thread = 4 nodes x 4 cols, FFMA2 via fma.rn.f32x2.
__global__ void __launch_bounds__(256) k_mmA(const float* __restrict__ W) {
    __shared__ float2 sWd[64 * 32];    // W[k][j] as float2 pairs: [k*32 + j/2]
    __shared__ float2 sx2[64 * 64];    // x duplicated: sx2[n*64+k] = (x,x)
    int t = threadIdx.x;
    int nbase = blockIdx.x * 64;
    // stage W as float2
#pragma unroll
    for (int i = t; i < 2048; i += 256) sWd[i] = ((const float2*)W)[i];
    // stage x duplicated
#pragma unroll
    for (int i = t; i < 4096; i += 256) {
        int n = i >> 6, k = i & 63;
        int gn = nbase + n;
        float v = (gn < NN) ? g_x[gn * 64 + k] : 0.f;
        sx2[i] = make_float2(v, v);
    }
    __syncthreads();
    int qg = t & 15;                   // col group: cols qg*4 .. qg*4+3
    int ng = (t >> 4) * 4;             // first of 4 nodes
    unsigned long long acc[4][2];
#pragma unroll
    for (int i = 0; i < 4; i++) { acc[i][0] = 0ull; acc[i][1] = 0ull; }

    const float2* wrow = sWd + qg * 2; // &W[k=0][cols qg*4..]
#pragma unroll 8
    for (int k = 0; k < 64; k++) {
        unsigned long long w01 = *(const unsigned long long*)(wrow + k * 32);
        unsigned long long w23 = *(const unsigned long long*)(wrow + k * 32 + 1);
#pragma unroll
        for (int i = 0; i < 4; i++) {
            unsigned long long xx = *(const unsigned long long*)(sx2 + (ng + i) * 64 + k);
            asm("fma.rn.f32x2 %0, %1, %2, %0;" : "+l"(acc[i][0]) : "l"(xx), "l"(w01));
            asm("fma.rn.f32x2 %0, %1, %2, %0;" : "+l"(acc[i][1]) : "l"(xx), "l"(w23));
        }
    }
#pragma unroll
    for (int i = 0; i < 4; i++) {
        int n = nbase + ng + i;
        if (n >= NN) break;
        float dv = g_dinv[n];
        float lo0, hi0, lo1, hi1;
        asm("mov.b64 {%0,%1}, %2;" : "=f"(lo0), "=f"(hi0) : "l"(acc[i][0]));
        asm("mov.b64 {%0,%1}, %2;" : "=f"(lo1), "=f"(hi1) : "l"(acc[i][1]));
        float4 o = make_float4(lo0 * dv, hi0 * dv, lo1 * dv, hi1 * dv);
        ((float4*)g_hs)[n * 16 + qg] = o;
    }
}

// ---------------- gather + finalize (layers 1,2): pull-mode, 32 lanes/node ----------------
__global__ void __launch_bounds__(256) k_gather(
        const float* __restrict__ b, const float* __restrict__ gm,
        const float* __restrict__ be, const float* __restrict__ rm,
        const float* __restrict__ rv) {
    int lane = threadIdx.x & 31;
    int node = blockIdx.x * 8 + (threadIdx.x >> 5);
    if (node >= NN) return;

    int j = lane * 2;
    float scx = gm[j] * rsqrtf(rv[j] + BN_EPS);
    float scy = gm[j + 1] * rsqrtf(rv[j + 1] + BN_EPS);
    float shx = (b[j] - rm[j]) * scx + be[j];
    float shy = (b[j + 1] - rm[j + 1]) * scy + be[j + 1];

    const float2* hs2 = (const float2*)g_hs;
    float2 acc = hs2[node * 32 + lane];      // self-loop term (hs = h*dinv)

    int beg = g_rowptr[node], end = g_rowptr[node + 1];
    const int* __restrict__ idx = g_csrsrc;
    int k = beg;
    for (; k + 4 <= end; k += 4) {
        int s0 = idx[k], s1 = idx[k + 1], s2 = idx[k + 2], s3 = idx[k + 3];
        float2 v0 = hs2[s0 * 32 + lane];
        float2 v1 = hs2[s1 * 32 + lane];
        float2 v2 = hs2[s2 * 32 + lane];
        float2 v3 = hs2[s3 * 32 + lane];
        acc.x += (v0.x + v1.x) + (v2.x + v3.x);
        acc.y += (v0.y + v1.y) + (v2.y + v3.y);
    }
    for (; k < end; k++) {
        float2 v = hs2[idx[k] * 32 + lane];
        acc.x += v.x; acc.y += v.y;
    }

    float dv = g_dinv[node];
    float2 o;
    o.x = fmaxf(fmaf(acc.x * dv, scx, shx), 0.f);
    o.y = fmaxf(fmaf(acc.y * dv, scy, shy), 0.f);
    ((float2*)g_x)[node * 32 + lane] = o;
}

// ---------------- pooling: sorted batch_idx -> run-length reduction ----------------
#define POOL_NB 128
__global__ void k_pool(const int* __restrict__ bidx) {
    int j = threadIdx.x;                // 64 threads = dims
    int n0 = blockIdx.x * POOL_NB;
    if (n0 >= NN) return;
    int cur = bidx[n0];
    float s = 0.f, mx = 0.f, c = 0.f;
    for (int i = 0; i < POOL_NB; i++) {
        int n = n0 + i;
        if (n >= NN) break;
        int gidx = bidx[n];
        if (gidx != cur) {
            atomicAdd(&g_gsum[cur * 64 + j], s);
            atomicMax(&g_gmax[cur * 64 + j], __float_as_int(mx));
            if (j == 0) atomicAdd(&g_gcnt[cur], c);
            cur = gidx; s = 0.f; mx = 0.f; c = 0.f;
        }
        float v = g_x[n * 64 + j];
        s += v;
        mx = fmaxf(mx, v);
        c += 1.f;
    }
    atomicAdd(&g_gsum[cur * 64 + j], s);
    atomicMax(&g_gmax[cur * 64 + j], __float_as_int(mx));
    if (j == 0) atomicAdd(&g_gcnt[cur], c);
}

// ---------------- MLP head ----------------
__global__ void k_mlp(const float* __restrict__ mW1, const float* __restrict__ mb1,
                      const float* __restrict__ mW2, const float* __restrict__ mb2,
                      const float* __restrict__ mW3, const float* __restrict__ mb3,
                      float* __restrict__ out) {
    __shared__ float xg[128];
    __shared__ float h1[32];
    __shared__ float h2[16];
    int g = blockIdx.x;
    int t = threadIdx.x;                // 32 threads
    float cnt = fmaxf(g_gcnt[g], 1.f);
    for (int j = t; j < 64; j += 32) {
        xg[j]      = g_gsum[g * 64 + j] / cnt;
        xg[64 + j] = __int_as_float(g_gmax[g * 64 + j]);
    }
    __syncthreads();
    {
        float acc = mb1[t];
        for (int k = 0; k < 128; k++) acc += xg[k] * mW1[k * 32 + t];
        h1[t] = fmaxf(acc, 0.f);
    }
    __syncthreads();
    if (t < 16) {
        float acc = mb2[t];
        for (int k = 0; k < 32; k++) acc += h1[k] * mW2[k * 16 + t];
        h2[t] = fmaxf(acc, 0.f);
    }
    __syncthreads();
    if (t == 0) {
        float acc = mb3[0];
        for (int k = 0; k < 16; k++) acc += h2[k] * mW3[k];
        out[g] = acc;
    }
}

extern "C" void kernel_launch(void* const* d_in, const int* in_sizes, int n_in,
                              void* d_out, int out_size) {
    const float* x    = (const float*)d_in[0];
    const int*   ei   = (const int*)  d_in[1];
    const int*   bidx = (const int*)  d_in[2];
    const float* W[3]  = {(const float*)d_in[3],  (const float*)d_in[9],  (const float*)d_in[15]};
    const float* b[3]  = {(const float*)d_in[4],  (const float*)d_in[10], (const float*)d_in[16]};
    const float* gm[3] = {(const float*)d_in[5],  (const float*)d_in[11], (const float*)d_in[17]};
    const float* be[3] = {(const float*)d_in[6],  (const float*)d_in[12], (const float*)d_in[18]};
    const float* rm[3] = {(const float*)d_in[7],  (const float*)d_in[13], (const float*)d_in[19]};
    const float* rv[3] = {(const float*)d_in[8],  (const float*)d_in[14], (const float*)d_in[20]};
    const float* mW1 = (const float*)d_in[21];
    const float* mb1 = (const float*)d_in[22];
    const float* mW2 = (const float*)d_in[23];
    const float* mb2 = (const float*)d_in[24];
    const float* mW3 = (const float*)d_in[25];
    const float* mb3 = (const float*)d_in[26];
    float* out = (float*)d_out;

    const int T = 256;
    int zmBlocks   = (NN + T - 1) / T;
    int degBlocks  = (EE + T - 1) / T;
    int g3Blocks   = (NN + T - 1) / T;
    int mm0Blocks  = (NN + 15) / 16;
    int mmABlocks  = (NN + 63) / 64;
    int gatBlocks  = (NN + 7) / 8;
    int poolBlocks = (NN + POOL_NB - 1) / POOL_NB;

    k_zero_misc<<<zmBlocks, T>>>();
    k_deg<<<degBlocks, T>>>(ei);
    k_scan1<<<SCAN_NB, SCAN_BS>>>();
    k_scan23<<<SCAN_NB, SCAN_BS>>>(x);
    k_csr<<<degBlocks, T>>>(ei);

    // layer 0: gather in 3-dim input space, then GEMM+BN+ReLU
    k_gather3<<<g3Blocks, T>>>();
    k_mm0f<<<mm0Blocks, T>>>(W[0], b[0], gm[0], be[0], rm[0], rv[0]);

    // layers 1, 2
    for (int l = 1; l < 3; l++) {
        k_mmA<<<mmABlocks, T>>>(W[l]);
        k_gather<<<gatBlocks, T>>>(b[l], gm[l], be[l], rm[l], rv[l]);
    }

    k_pool<<<poolBlocks, 64>>>(bidx);
    k_mlp<<<GG, 32>>>(mW1, mb1, mW2, mb2, mW3, mb3, out);
}

// round 6
// speedup vs baseline: 2.4073x; 1.0219x over previous
#include <cuda_runtime.h>
#include <cuda_fp16.h>
#include <cuda_bf16.h>

#define NN 100000
#define EE 1600000
#define GG 256
#define HH 64
#define BN_EPS 1e-5f
#define SCAN_BS 512
#define SCAN_NB ((NN + SCAN_BS - 1) / SCAN_BS)   // 196

// ---------------- scratch (device globals; no allocation) ----------------
__device__ int     g_deg[NN];
__device__ float   g_dinv[NN];
__device__ float4  g_xs[NN];          // dinv * x (3-wide, w=0)
__device__ float4  g_aggx[NN];        // layer-0 aggregated input features
__device__ __half2 g_hsh[NN * 32];    // (x @ W) * dinv, fp16 storage (64 dims = 32 half2)
__device__ float   g_x[NN * HH];      // layer activations (fp32)
__device__ int     g_rowptr[NN + 1];
__device__ int     g_cursor[NN];
__device__ int     g_csrsrc[EE];
__device__ int     g_ptmp[NN];
__device__ int     g_bsum[SCAN_NB];
__device__ float   g_gsum[GG * HH];
__device__ int     g_gmax[GG * HH];
__device__ float   g_gcnt[GG];

// ---------------- zeroing ----------------
__global__ void k_zero_misc() {
    int i = blockIdx.x * blockDim.x + threadIdx.x;
    if (i < NN) g_deg[i] = 0;
    if (i < GG * HH) { g_gsum[i] = 0.f; g_gmax[i] = 0; }
    if (i < GG) g_gcnt[i] = 0.f;
}

// ---------------- degree histogram (by dst) ----------------
__global__ void k_deg(const int* __restrict__ ei) {
    int e = blockIdx.x * blockDim.x + threadIdx.x;
    if (e < EE) atomicAdd(&g_deg[ei[EE + e]], 1);
}

// ---------------- scan part 1: per-block inclusive scan + block sums ----------------
__global__ void k_scan1() {
    __shared__ int s[SCAN_BS];
    int i = blockIdx.x * SCAN_BS + threadIdx.x;
    int v = (i < NN) ? g_deg[i] : 0;
    s[threadIdx.x] = v;
    __syncthreads();
    for (int off = 1; off < SCAN_BS; off <<= 1) {
        int t = s[threadIdx.x];
        if (threadIdx.x >= off) t += s[threadIdx.x - off];
        __syncthreads();
        s[threadIdx.x] = t;
        __syncthreads();
    }
    if (i < NN) g_ptmp[i] = s[threadIdx.x];
    if (threadIdx.x == SCAN_BS - 1) g_bsum[blockIdx.x] = s[threadIdx.x];
}

// ---------------- scan part 2 (fused): block offset + rowptr/cursor/dinv/xs ----------------
__global__ void k_scan23(const float* __restrict__ x) {
    __shared__ int r[SCAN_BS];
    int t = threadIdx.x;
    r[t] = (t < SCAN_NB && t < blockIdx.x) ? g_bsum[t] : 0;
    __syncthreads();
    for (int off = SCAN_BS / 2; off > 0; off >>= 1) {
        if (t < off) r[t] += r[t + off];
        __syncthreads();
    }
    int boff = r[0];
    int i = blockIdx.x * SCAN_BS + t;
    if (i < NN) {
        int d = g_deg[i];
        int excl = g_ptmp[i] + boff - d;
        g_rowptr[i] = excl;
        g_cursor[i] = excl;
        float dv = rsqrtf((float)d + 1.0f);
        g_dinv[i] = dv;
        g_xs[i] = make_float4(x[i * 3] * dv, x[i * 3 + 1] * dv, x[i * 3 + 2] * dv, 0.f);
    }
    if (i == 0) g_rowptr[NN] = EE;
}

// ---------------- CSR fill ----------------
__global__ void k_csr(const int* __restrict__ ei) {
    int e = blockIdx.x * blockDim.x + threadIdx.x;
    if (e < EE) {
        int s = ei[e];
        int d = ei[EE + e];
        int p = atomicAdd(&g_cursor[d], 1);
        g_csrsrc[p] = s;
    }
}

// ---------------- layer-0 gather in INPUT space (3-wide): tiny traffic ----------------
__global__ void k_gather3() {
    int node = blockIdx.x * blockDim.x + threadIdx.x;
    if (node >= NN) return;
    float4 acc = g_xs[node];                 // self term xs_d
    int beg = g_rowptr[node], end = g_rowptr[node + 1];
    const int* __restrict__ idx = g_csrsrc;
    int k = beg;
    for (; k + 4 <= end; k += 4) {
        int s0 = idx[k], s1 = idx[k + 1], s2 = idx[k + 2], s3 = idx[k + 3];
        float4 a = g_xs[s0], b = g_xs[s1], c = g_xs[s2], d = g_xs[s3];
        acc.x += (a.x + b.x) + (c.x + d.x);
        acc.y += (a.y + b.y) + (c.y + d.y);
        acc.z += (a.z + b.z) + (c.z + d.z);
    }
    for (; k < end; k++) {
        float4 a = g_xs[idx[k]];
        acc.x += a.x; acc.y += a.y; acc.z += a.z;
    }
    float dv = g_dinv[node];
    g_aggx[node] = make_float4(acc.x * dv, acc.y * dv, acc.z * dv, 0.f);
}

// ---------------- layer-0 GEMM + bias + BN + ReLU -> g_x ----------------
__global__ void __launch_bounds__(256) k_mm0f(const float* __restrict__ W0,
        const float* __restrict__ b, const float* __restrict__ gm,
        const float* __restrict__ be, const float* __restrict__ rm,
        const float* __restrict__ rv) {
    __shared__ float4 sW4[3][16];
    __shared__ float4 sxa[16];
    int t = threadIdx.x;
    if (t < 48) sW4[t / 16][t % 16] = ((const float4*)W0)[t];
    if (t < 16) {
        int gn = blockIdx.x * 16 + t;
        sxa[t] = (gn < NN) ? g_aggx[gn] : make_float4(0.f, 0.f, 0.f, 0.f);
    }
    __syncthreads();
    int nl = t >> 4, q = t & 15;
    int n = blockIdx.x * 16 + nl;
    if (n >= NN) return;
    int j = q * 4;
    float4 sc, sh;
    sc.x = gm[j] * rsqrtf(rv[j] + BN_EPS);
    sc.y = gm[j + 1] * rsqrtf(rv[j + 1] + BN_EPS);
    sc.z = gm[j + 2] * rsqrtf(rv[j + 2] + BN_EPS);
    sc.w = gm[j + 3] * rsqrtf(rv[j + 3] + BN_EPS);
    sh.x = (b[j] - rm[j]) * sc.x + be[j];
    sh.y = (b[j + 1] - rm[j + 1]) * sc.y + be[j + 1];
    sh.z = (b[j + 2] - rm[j + 2]) * sc.z + be[j + 2];
    sh.w = (b[j + 3] - rm[j + 3]) * sc.w + be[j + 3];
    float4 a = sxa[nl];
    float4 w0 = sW4[0][q], w1 = sW4[1][q], w2 = sW4[2][q];
    float4 o;
    o.x = fmaxf(fmaf(a.x * w0.x + a.y * w1.x + a.z * w2.x, sc.x, sh.x), 0.f);
    o.y = fmaxf(fmaf(a.x * w0.y + a.y * w1.y + a.z * w2.y, sc.y, sh.y), 0.f);
    o.z = fmaxf(fmaf(a.x * w0.z + a.y * w1.z + a.z * w2.z, sc.z, sh.z), 0.f);
    o.w = fmaxf(fmaf(a.x * w0.w + a.y * w1.w + a.z * w2.w, sc.w, sh.w), 0.f);
    ((float4*)g_x)[n * 16 + q] = o;
}

// ---------------- layers 1,2 GEMM: hs = (g_x @ W) * dinv ; packed f32x2, fp16 out ----------------
__global__ void __launch_bounds__(256) k_mmA(const float* __restrict__ W) {
    __shared__ float2 sWd[64 * 32];    // W[k][j] as float2 pairs
    __shared__ float2 sx2[64 * 64];    // x duplicated: sx2[n*64+k] = (x,x)
    int t = threadIdx.x;
    int nbase = blockIdx.x * 64;
#pragma unroll
    for (int i = t; i < 2048; i += 256) sWd[i] = ((const float2*)W)[i];
#pragma unroll
    for (int i = t; i < 4096; i += 256) {
        int n = i >> 6, k = i & 63;
        int gn = nbase + n;
        float v = (gn < NN) ? g_x[gn * 64 + k] : 0.f;
        sx2[i] = make_float2(v, v);
    }
    __syncthreads();
    int qg = t & 15;                   // col group: cols qg*4 .. qg*4+3
    int ng = (t >> 4) * 4;             // first of 4 nodes
    unsigned long long acc[4][2];
#pragma unroll
    for (int i = 0; i < 4; i++) { acc[i][0] = 0ull; acc[i][1] = 0ull; }

    const float2* wrow = sWd + qg * 2;
#pragma unroll 8
    for (int k = 0; k < 64; k++) {
        unsigned long long w01 = *(const unsigned long long*)(wrow + k * 32);
        unsigned long long w23 = *(const unsigned long long*)(wrow + k * 32 + 1);
#pragma unroll
        for (int i = 0; i < 4; i++) {
            unsigned long long xx = *(const unsigned long long*)(sx2 + (ng + i) * 64 + k);
            asm("fma.rn.f32x2 %0, %1, %2, %0;" : "+l"(acc[i][0]) : "l"(xx), "l"(w01));
            asm("fma.rn.f32x2 %0, %1, %2, %0;" : "+l"(acc[i][1]) : "l"(xx), "l"(w23));
        }
    }
#pragma unroll
    for (int i = 0; i < 4; i++) {
        int n = nbase + ng + i;
        if (n >= NN) break;
        float dv = g_dinv[n];
        float lo0, hi0, lo1, hi1;
        asm("mov.b64 {%0,%1}, %2;" : "=f"(lo0), "=f"(hi0) : "l"(acc[i][0]));
        asm("mov.b64 {%0,%1}, %2;" : "=f"(lo1), "=f"(hi1) : "l"(acc[i][1]));
        __half2 h0 = __float22half2_rn(make_float2(lo0 * dv, hi0 * dv));
        __half2 h1 = __float22half2_rn(make_float2(lo1 * dv, hi1 * dv));
        uint2 packed = make_uint2(reinterpret_cast<unsigned&>(h0),
                                  reinterpret_cast<unsigned&>(h1));
        ((uint2*)g_hsh)[n * 16 + qg] = packed;
    }
}

// ---------------- gather + finalize (layers 1,2): fp16 reads, fp32 accumulate ----------------
__global__ void __launch_bounds__(256) k_gather(
        const float* __restrict__ b, const float* __restrict__ gm,
        const float* __restrict__ be, const float* __restrict__ rm,
        const float* __restrict__ rv) {
    int lane = threadIdx.x & 31;
    int node = blockIdx.x * 8 + (threadIdx.x >> 5);
    if (node >= NN) return;

    int j = lane * 2;
    float scx = gm[j] * rsqrtf(rv[j] + BN_EPS);
    float scy = gm[j + 1] * rsqrtf(rv[j + 1] + BN_EPS);
    float shx = (b[j] - rm[j]) * scx + be[j];
    float shy = (b[j + 1] - rm[j + 1]) * scy + be[j + 1];

    const __half2* __restrict__ hs2 = g_hsh;
    float2 acc = __half22float2(hs2[node * 32 + lane]);   // self-loop term

    int beg = g_rowptr[node], end = g_rowptr[node + 1];
    const int* __restrict__ idx = g_csrsrc;
    int k = beg;
    for (; k + 4 <= end; k += 4) {
        int s0 = idx[k], s1 = idx[k + 1], s2 = idx[k + 2], s3 = idx[k + 3];
        float2 v0 = __half22float2(hs2[s0 * 32 + lane]);
        float2 v1 = __half22float2(hs2[s1 * 32 + lane]);
        float2 v2 = __half22float2(hs2[s2 * 32 + lane]);
        float2 v3 = __half22float2(hs2[s3 * 32 + lane]);
        acc.x += (v0.x + v1.x) + (v2.x + v3.x);
        acc.y += (v0.y + v1.y) + (v2.y + v3.y);
    }
    for (; k < end; k++) {
        float2 v = __half22float2(hs2[idx[k] * 32 + lane]);
        acc.x += v.x; acc.y += v.y;
    }

    float dv = g_dinv[node];
    float2 o;
    o.x = fmaxf(fmaf(acc.x * dv, scx, shx), 0.f);
    o.y = fmaxf(fmaf(acc.y * dv, scy, shy), 0.f);
    ((float2*)g_x)[node * 32 + lane] = o;
}

// ---------------- pooling: sorted batch_idx -> run-length reduction ----------------
#define POOL_NB 128
__global__ void k_pool(const int* __restrict__ bidx) {
    int j = threadIdx.x;                // 64 threads = dims
    int n0 = blockIdx.x * POOL_NB;
    if (n0 >= NN) return;
    int cur = bidx[n0];
    float s = 0.f, mx = 0.f, c = 0.f;
    for (int i = 0; i < POOL_NB; i++) {
        int n = n0 + i;
        if (n >= NN) break;
        int gidx = bidx[n];
        if (gidx != cur) {
            atomicAdd(&g_gsum[cur * 64 + j], s);
            atomicMax(&g_gmax[cur * 64 + j], __float_as_int(mx));
            if (j == 0) atomicAdd(&g_gcnt[cur], c);
            cur = gidx; s = 0.f; mx = 0.f; c = 0.f;
        }
        float v = g_x[n * 64 + j];
        s += v;
        mx = fmaxf(mx, v);
        c += 1.f;
    }
    atomicAdd(&g_gsum[cur * 64 + j], s);
    atomicMax(&g_gmax[cur * 64 + j], __float_as_int(mx));
    if (j == 0) atomicAdd(&g_gcnt[cur], c);
}

// ---------------- MLP head ----------------
__global__ void k_mlp(const float* __restrict__ mW1, const float* __restrict__ mb1,
                      const float* __restrict__ mW2, const float* __restrict__ mb2,
                      const float* __restrict__ mW3, const float* __restrict__ mb3,
                      float* __restrict__ out) {
    __shared__ float xg[128];
    __shared__ float h1[32];
    __shared__ float h2[16];
    int g = blockIdx.x;
    int t = threadIdx.x;                // 32 threads
    float cnt = fmaxf(g_gcnt[g], 1.f);
    for (int j = t; j < 64; j += 32) {
        xg[j]      = g_gsum[g * 64 + j] / cnt;
        xg[64 + j] = __int_as_float(g_gmax[g * 64 + j]);
    }
    __syncthreads();
    {
        float acc = mb1[t];
        for (int k = 0; k < 128; k++) acc += xg[k] * mW1[k * 32 + t];
        h1[t] = fmaxf(acc, 0.f);
    }
    __syncthreads();
    if (t < 16) {
        float acc = mb2[t];
        for (int k = 0; k < 32; k++) acc += h1[k] * mW2[k * 16 + t];
        h2[t] = fmaxf(acc, 0.f);
    }
    __syncthreads();
    if (t == 0) {
        float acc = mb3[0];
        for (int k = 0; k < 16; k++) acc += h2[k] * mW3[k];
        out[g] = acc;
    }
}

extern "C" void kernel_launch(void* const* d_in, const int* in_sizes, int n_in,
                              void* d_out, int out_size) {
    const float* x    = (const float*)d_in[0];
    const int*   ei   = (const int*)  d_in[1];
    const int*   bidx = (const int*)  d_in[2];
    const float* W[3]  = {(const float*)d_in[3],  (const float*)d_in[9],  (const float*)d_in[15]};
    const float* b[3]  = {(const float*)d_in[4],  (const float*)d_in[10], (const float*)d_in[16]};
    const float* gm[3] = {(const float*)d_in[5],  (const float*)d_in[11], (const float*)d_in[17]};
    const float* be[3] = {(const float*)d_in[6],  (const float*)d_in[12], (const float*)d_in[18]};
    const float* rm[3] = {(const float*)d_in[7],  (const float*)d_in[13], (const float*)d_in[19]};
    const float* rv[3] = {(const float*)d_in[8],  (const float*)d_in[14], (const float*)d_in[20]};
    const float* mW1 = (const float*)d_in[21];
    const float* mb1 = (const float*)d_in[22];
    const float* mW2 = (const float*)d_in[23];
    const float* mb2 = (const float*)d_in[24];
    const float* mW3 = (const float*)d_in[25];
    const float* mb3 = (const float*)d_in[26];
    float* out = (float*)d_out;

    const int T = 256;
    int zmBlocks   = (NN + T - 1) / T;
    int degBlocks  = (EE + T - 1) / T;
    int g3Blocks   = (NN + T - 1) / T;
    int mm0Blocks  = (NN + 15) / 16;
    int mmABlocks  = (NN + 63) / 64;
    int gatBlocks  = (NN + 7) / 8;
    int poolBlocks = (NN + POOL_NB - 1) / POOL_NB;

    k_zero_misc<<<zmBlocks, T>>>();
    k_deg<<<degBlocks, T>>>(ei);
    k_scan1<<<SCAN_NB, SCAN_BS>>>();
    k_scan23<<<SCAN_NB, SCAN_BS>>>(x);
    k_csr<<<degBlocks, T>>>(ei);

    // layer 0: gather in 3-dim input space, then GEMM+BN+ReLU
    k_gather3<<<g3Blocks, T>>>();
    k_mm0f<<<mm0Blocks, T>>>(W[0], b[0], gm[0], be[0], rm[0], rv[0]);

    // layers 1, 2
    for (int l = 1; l < 3; l++) {
        k_mmA<<<mmABlocks, T>>>(W[l]);
        k_gather<<<gatBlocks, T>>>(b[l], gm[l], be[l], rm[l], rv[l]);
    }

    k_pool<<<poolBlocks, 64>>>(bidx);
    k_mlp<<<GG, 32>>>(mW1, mb1, mW2, mb2, mW3, mb3, out);
}

// round 7
// speedup vs baseline: 2.4533x; 1.0191x over previous
#include <cuda_runtime.h>
#include <cuda_fp16.h>
#include <cuda_bf16.h>

#define NN 100000
#define EE 1600000
#define GG 256
#define HH 64
#define BN_EPS 1e-5f

// ---------------- scratch (device globals; zero-initialized at load) ----------------
__device__ int     g_deg[NN];          // re-zeroed by k_csr each run
__device__ int     g_total;            // re-zeroed by k_csr each run
__device__ float   g_dinv[NN];
__device__ float4  g_xs[NN];           // dinv * x (3-wide, w=0)
__device__ __half2 g_hsh[NN * 32];     // (x @ W) * dinv, fp16 (64 dims = 32 half2)
__device__ float   g_x[NN * HH];       // layer activations (fp32)
__device__ int     g_rowptr[NN];
__device__ int     g_rowend[NN];
__device__ int     g_cursor[NN];
__device__ int     g_csrsrc[EE];
__device__ float   g_gsum[GG * HH];    // re-zeroed by k_mlp each run
__device__ int     g_gmax[GG * HH];    // re-zeroed by k_mlp each run
__device__ float   g_gcnt[GG];         // re-zeroed by k_mlp each run

// ---------------- degree histogram (by dst) ----------------
__global__ void k_deg(const int* __restrict__ ei) {
    int e = blockIdx.x * blockDim.x + threadIdx.x;
    if (e < EE) atomicAdd(&g_deg[ei[EE + e]], 1);
}

// ---------------- CSR slot allocation: warp-aggregated atomic, no scan ----------------
__global__ void k_alloc(const float* __restrict__ x) {
    int i = blockIdx.x * blockDim.x + threadIdx.x;
    int lane = threadIdx.x & 31;
    int d = (i < NN) ? g_deg[i] : 0;
    int incl = d;
#pragma unroll
    for (int off = 1; off < 32; off <<= 1) {
        int v = __shfl_up_sync(0xffffffffu, incl, off);
        if (lane >= off) incl += v;
    }
    int total = __shfl_sync(0xffffffffu, incl, 31);
    int base = 0;
    if (lane == 31) base = atomicAdd(&g_total, total);
    base = __shfl_sync(0xffffffffu, base, 31);
    int excl = base + incl - d;
    if (i < NN) {
        g_rowptr[i] = excl;
        g_rowend[i] = excl + d;
        g_cursor[i] = excl;
        float dv = rsqrtf((float)d + 1.0f);
        g_dinv[i] = dv;
        g_xs[i] = make_float4(x[i * 3] * dv, x[i * 3 + 1] * dv, x[i * 3 + 2] * dv, 0.f);
    }
}

// ---------------- CSR fill (+ cleanup of deg/total for next replay) ----------------
__global__ void k_csr(const int* __restrict__ ei) {
    int e = blockIdx.x * blockDim.x + threadIdx.x;
    if (e < NN) g_deg[e] = 0;          // deg no longer needed this run
    if (e == 0) g_total = 0;
    if (e < EE) {
        int s = ei[e];
        int d = ei[EE + e];
        int p = atomicAdd(&g_cursor[d], 1);
        g_csrsrc[p] = s;
    }
}

// ---------------- layer 0 fused: input-space gather + GEMM + BN + ReLU -> g_x ----------------
__global__ void __launch_bounds__(256) k_layer0(const float* __restrict__ W0,
        const float* __restrict__ b, const float* __restrict__ gm,
        const float* __restrict__ be, const float* __restrict__ rm,
        const float* __restrict__ rv) {
    __shared__ float sW[192];
    __shared__ float sxa[256][3];
    int t = threadIdx.x;
    if (t < 192) sW[t] = W0[t];
    int n = blockIdx.x * 256 + t;

    // phase 1: per-node gather of 3-wide scaled inputs
    float ax = 0.f, ay = 0.f, az = 0.f;
    if (n < NN) {
        float4 self = g_xs[n];
        ax = self.x; ay = self.y; az = self.z;
        int beg = g_rowptr[n], end = g_rowend[n];
        const int* __restrict__ idx = g_csrsrc;
        int k = beg;
        for (; k + 4 <= end; k += 4) {
            int s0 = idx[k], s1 = idx[k + 1], s2 = idx[k + 2], s3 = idx[k + 3];
            float4 a = g_xs[s0], bb = g_xs[s1], c = g_xs[s2], d = g_xs[s3];
            ax += (a.x + bb.x) + (c.x + d.x);
            ay += (a.y + bb.y) + (c.y + d.y);
            az += (a.z + bb.z) + (c.z + d.z);
        }
        for (; k < end; k++) {
            float4 a = g_xs[idx[k]];
            ax += a.x; ay += a.y; az += a.z;
        }
        float dv = g_dinv[n];
        ax *= dv; ay *= dv; az *= dv;
    }
    sxa[t][0] = ax; sxa[t][1] = ay; sxa[t][2] = az;
    __syncthreads();

    // phase 2: GEMM 3->64 + BN + ReLU, 16 nodes x 16 float4-cols per round
    int q = t & 15;
    int j = q * 4;
    float4 sc, sh;
    sc.x = gm[j] * rsqrtf(rv[j] + BN_EPS);
    sc.y = gm[j + 1] * rsqrtf(rv[j + 1] + BN_EPS);
    sc.z = gm[j + 2] * rsqrtf(rv[j + 2] + BN_EPS);
    sc.w = gm[j + 3] * rsqrtf(rv[j + 3] + BN_EPS);
    sh.x = (b[j] - rm[j]) * sc.x + be[j];
    sh.y = (b[j + 1] - rm[j + 1]) * sc.y + be[j + 1];
    sh.z = (b[j + 2] - rm[j + 2]) * sc.z + be[j + 2];
    sh.w = (b[j + 3] - rm[j + 3]) * sc.w + be[j + 3];
    float w0x = sW[j],       w0y = sW[j + 1],       w0z = sW[j + 2],       w0w = sW[j + 3];
    float w1x = sW[64 + j],  w1y = sW[64 + j + 1],  w1z = sW[64 + j + 2],  w1w = sW[64 + j + 3];
    float w2x = sW[128 + j], w2y = sW[128 + j + 1], w2z = sW[128 + j + 2], w2w = sW[128 + j + 3];
#pragma unroll
    for (int r = 0; r < 16; r++) {
        int nl = r * 16 + (t >> 4);
        int gn = blockIdx.x * 256 + nl;
        if (gn >= NN) break;
        float a0 = sxa[nl][0], a1 = sxa[nl][1], a2 = sxa[nl][2];
        float4 o;
        o.x = fmaxf(fmaf(a0 * w0x + a1 * w1x + a2 * w2x, sc.x, sh.x), 0.f);
        o.y = fmaxf(fmaf(a0 * w0y + a1 * w1y + a2 * w2y, sc.y, sh.y), 0.f);
        o.z = fmaxf(fmaf(a0 * w0z + a1 * w1z + a2 * w2z, sc.z, sh.z), 0.f);
        o.w = fmaxf(fmaf(a0 * w0w + a1 * w1w + a2 * w2w, sc.w, sh.w), 0.f);
        ((float4*)g_x)[gn * 16 + q] = o;
    }
}

// ---------------- layers 1,2 GEMM: hs = (g_x @ W) * dinv ; packed f32x2, fp16 out ----------------
__global__ void __launch_bounds__(256) k_mmA(const float* __restrict__ W) {
    __shared__ float2 sWd[64 * 32];    // W[k][j] as float2 pairs
    __shared__ float2 sx2[64 * 64];    // x duplicated: sx2[n*64+k] = (x,x)
    int t = threadIdx.x;
    int nbase = blockIdx.x * 64;
#pragma unroll
    for (int i = t; i < 2048; i += 256) sWd[i] = ((const float2*)W)[i];
#pragma unroll
    for (int i = t; i < 1024; i += 256) {
        int n = i >> 4, q = i & 15;
        int gn = nbase + n;
        float4 v = (gn < NN) ? ((const float4*)g_x)[gn * 16 + q]
                             : make_float4(0.f, 0.f, 0.f, 0.f);
        float2* dst = sx2 + n * 64 + q * 4;
        dst[0] = make_float2(v.x, v.x);
        dst[1] = make_float2(v.y, v.y);
        dst[2] = make_float2(v.z, v.z);
        dst[3] = make_float2(v.w, v.w);
    }
    __syncthreads();
    int qg = t & 15;                   // col group: cols qg*4 .. qg*4+3
    int ng = (t >> 4) * 4;             // first of 4 nodes
    unsigned long long acc[4][2];
#pragma unroll
    for (int i = 0; i < 4; i++) { acc[i][0] = 0ull; acc[i][1] = 0ull; }

    const float2* wrow = sWd + qg * 2;
#pragma unroll 8
    for (int k = 0; k < 64; k++) {
        unsigned long long w01 = *(const unsigned long long*)(wrow + k * 32);
        unsigned long long w23 = *(const unsigned long long*)(wrow + k * 32 + 1);
#pragma unroll
        for (int i = 0; i < 4; i++) {
            unsigned long long xx = *(const unsigned long long*)(sx2 + (ng + i) * 64 + k);
            asm("fma.rn.f32x2 %0, %1, %2, %0;" : "+l"(acc[i][0]) : "l"(xx), "l"(w01));
            asm("fma.rn.f32x2 %0, %1, %2, %0;" : "+l"(acc[i][1]) : "l"(xx), "l"(w23));
        }
    }
#pragma unroll
    for (int i = 0; i < 4; i++) {
        int n = nbase + ng + i;
        if (n >= NN) break;
        float dv = g_dinv[n];
        float lo0, hi0, lo1, hi1;
        asm("mov.b64 {%0,%1}, %2;" : "=f"(lo0), "=f"(hi0) : "l"(acc[i][0]));
        asm("mov.b64 {%0,%1}, %2;" : "=f"(lo1), "=f"(hi1) : "l"(acc[i][1]));
        __half2 h0 = __float22half2_rn(make_float2(lo0 * dv, hi0 * dv));
        __half2 h1 = __float22half2_rn(make_float2(lo1 * dv, hi1 * dv));
        uint2 packed = make_uint2(reinterpret_cast<unsigned&>(h0),
                                  reinterpret_cast<unsigned&>(h1));
        ((uint2*)g_hsh)[n * 16 + qg] = packed;
    }
}

// ---------------- gather + finalize (layers 1,2): lane-batched idx + shfl ----------------
__global__ void __launch_bounds__(256) k_gather(
        const float* __restrict__ b, const float* __restrict__ gm,
        const float* __restrict__ be, const float* __restrict__ rm,
        const float* __restrict__ rv) {
    int lane = threadIdx.x & 31;
    int node = blockIdx.x * 8 + (threadIdx.x >> 5);
    if (node >= NN) return;

    int j = lane * 2;
    float scx = gm[j] * rsqrtf(rv[j] + BN_EPS);
    float scy = gm[j + 1] * rsqrtf(rv[j + 1] + BN_EPS);
    float shx = (b[j] - rm[j]) * scx + be[j];
    float shy = (b[j + 1] - rm[j + 1]) * scy + be[j + 1];

    const __half2* __restrict__ hs2 = g_hsh;
    float2 acc = __half22float2(hs2[node * 32 + lane]);   // self-loop term

    int beg = g_rowptr[node];
    int m = g_rowend[node] - beg;
    const int* __restrict__ idx = g_csrsrc + beg;

    for (int base = 0; base < m; base += 32) {
        int rem = m - base;
        int cnt = (rem < 32) ? rem : 32;
        int myidx = (lane < cnt) ? idx[base + lane] : 0;
        int k = 0;
        for (; k + 4 <= cnt; k += 4) {
            int s0 = __shfl_sync(0xffffffffu, myidx, k);
            int s1 = __shfl_sync(0xffffffffu, myidx, k + 1);
            int s2 = __shfl_sync(0xffffffffu, myidx, k + 2);
            int s3 = __shfl_sync(0xffffffffu, myidx, k + 3);
            float2 v0 = __half22float2(hs2[s0 * 32 + lane]);
            float2 v1 = __half22float2(hs2[s1 * 32 + lane]);
            float2 v2 = __half22float2(hs2[s2 * 32 + lane]);
            float2 v3 = __half22float2(hs2[s3 * 32 + lane]);
            acc.x += (v0.x + v1.x) + (v2.x + v3.x);
            acc.y += (v0.y + v1.y) + (v2.y + v3.y);
        }
        for (; k < cnt; k++) {
            int s = __shfl_sync(0xffffffffu, myidx, k);
            float2 v = __half22float2(hs2[s * 32 + lane]);
            acc.x += v.x; acc.y += v.y;
        }
    }

    float dv = g_dinv[node];
    float2 o;
    o.x = fmaxf(fmaf(acc.x * dv, scx, shx), 0.f);
    o.y = fmaxf(fmaf(acc.y * dv, scy, shy), 0.f);
    ((float2*)g_x)[node * 32 + lane] = o;
}

// ---------------- pooling: sorted batch_idx -> run-length reduction ----------------
#define POOL_NB 128
__global__ void k_pool(const int* __restrict__ bidx) {
    int j = threadIdx.x;                // 64 threads = dims
    int n0 = blockIdx.x * POOL_NB;
    if (n0 >= NN) return;
    int cur = bidx[n0];
    float s = 0.f, mx = 0.f, c = 0.f;
    for (int i = 0; i < POOL_NB; i++) {
        int n = n0 + i;
        if (n >= NN) break;
        int gidx = bidx[n];
        if (gidx != cur) {
            atomicAdd(&g_gsum[cur * 64 + j], s);
            atomicMax(&g_gmax[cur * 64 + j], __float_as_int(mx));
            if (j == 0) atomicAdd(&g_gcnt[cur], c);
            cur = gidx; s = 0.f; mx = 0.f; c = 0.f;
        }
        float v = g_x[n * 64 + j];
        s += v;
        mx = fmaxf(mx, v);
        c += 1.f;
    }
    atomicAdd(&g_gsum[cur * 64 + j], s);
    atomicMax(&g_gmax[cur * 64 + j], __float_as_int(mx));
    if (j == 0) atomicAdd(&g_gcnt[cur], c);
}

// ---------------- MLP head (+ cleanup of pooling accumulators) ----------------
__global__ void k_mlp(const float* __restrict__ mW1, const float* __restrict__ mb1,
                      const float* __restrict__ mW2, const float* __restrict__ mb2,
                      const float* __restrict__ mW3, const float* __restrict__ mb3,
                      float* __restrict__ out) {
    __shared__ float xg[128];
    __shared__ float h1[32];
    __shared__ float h2[16];
    int g = blockIdx.x;
    int t = threadIdx.x;                // 32 threads
    float cnt = fmaxf(g_gcnt[g], 1.f);
    for (int j = t; j < 64; j += 32) {
        xg[j]      = g_gsum[g * 64 + j] / cnt;
        xg[64 + j] = __int_as_float(g_gmax[g * 64 + j]);
    }
    __syncthreads();
    // cleanup for next replay (reads above are done)
    for (int j = t; j < 64; j += 32) {
        g_gsum[g * 64 + j] = 0.f;
        g_gmax[g * 64 + j] = 0;
    }
    if (t == 0) g_gcnt[g] = 0.f;
    {
        float acc = mb1[t];
        for (int k = 0; k < 128; k++) acc += xg[k] * mW1[k * 32 + t];
        h1[t] = fmaxf(acc, 0.f);
    }
    __syncthreads();
    if (t < 16) {
        float acc = mb2[t];
        for (int k = 0; k < 32; k++) acc += h1[k] * mW2[k * 16 + t];
        h2[t] = fmaxf(acc, 0.f);
    }
    __syncthreads();
    if (t == 0) {
        float acc = mb3[0];
        for (int k = 0; k < 16; k++) acc += h2[k] * mW3[k];
        out[g] = acc;
    }
}

extern "C" void kernel_launch(void* const* d_in, const int* in_sizes, int n_in,
                              void* d_out, int out_size) {
    const float* x    = (const float*)d_in[0];
    const int*   ei   = (const int*)  d_in[1];
    const int*   bidx = (const int*)  d_in[2];
    const float* W[3]  = {(const float*)d_in[3],  (const float*)d_in[9],  (const float*)d_in[15]};
    const float* b[3]  = {(const float*)d_in[4],  (const float*)d_in[10], (const float*)d_in[16]};
    const float* gm[3] = {(const float*)d_in[5],  (const float*)d_in[11], (const float*)d_in[17]};
    const float* be[3] = {(const float*)d_in[6],  (const float*)d_in[12], (const float*)d_in[18]};
    const float* rm[3] = {(const float*)d_in[7],  (const float*)d_in[13], (const float*)d_in[19]};
    const float* rv[3] = {(const float*)d_in[8],  (const float*)d_in[14], (const float*)d_in[20]};
    const float* mW1 = (const float*)d_in[21];
    const float* mb1 = (const float*)d_in[22];
    const float* mW2 = (const float*)d_in[23];
    const float* mb2 = (const float*)d_in[24];
    const float* mW3 = (const float*)d_in[25];
    const float* mb3 = (const float*)d_in[26];
    float* out = (float*)d_out;

    const int T = 256;
    int degBlocks  = (EE + T - 1) / T;
    int nBlocks    = (NN + T - 1) / T;
    int l0Blocks   = (NN + 255) / 256;
    int mmABlocks  = (NN + 63) / 64;
    int gatBlocks  = (NN + 7) / 8;
    int poolBlocks = (NN + POOL_NB - 1) / POOL_NB;

    k_deg<<<degBlocks, T>>>(ei);
    k_alloc<<<nBlocks, T>>>(x);
    k_csr<<<degBlocks, T>>>(ei);

    k_layer0<<<l0Blocks, 256>>>(W[0], b[0], gm[0], be[0], rm[0], rv[0]);

    for (int l = 1; l < 3; l++) {
        k_mmA<<<mmABlocks, T>>>(W[l]);
        k_gather<<<gatBlocks, T>>>(b[l], gm[l], be[l], rm[l], rv[l]);
    }

    k_pool<<<poolBlocks, 64>>>(bidx);
    k_mlp<<<GG, 32>>>(mW1, mb1, mW2, mb2, mW3, mb3, out);
}